// round 11
// baseline (speedup 1.0000x reference)
#include <cuda_runtime.h>
#include <cstdint>

// Problem constants (fixed by reference setup_inputs)
#define BATCH   4
#define SEQ     2048
#define DMODEL  1024
#define DPROJ   256

#define BKF     32    // K-floats per smem tile
#define LDSP    36    // padded smem row stride (words): bank=(4*row+k)%32 -> conflict-free

// Scratch for h = relu(hidden @ proj_w^T + b): [B, S, P] fp32 = 8 MB
__device__ float g_h[BATCH * SEQ * DPROJ];

__device__ __forceinline__ uint32_t f2tf32(float x) {
    uint32_t r;
    asm("cvt.rna.tf32.f32 %0, %1;" : "=r"(r) : "f"(x));
    return r;
}

#define MMA_TF32(d, a, b)                                                      \
    asm volatile(                                                              \
        "mma.sync.aligned.m16n8k8.row.col.f32.tf32.tf32.f32 "                  \
        "{%0,%1,%2,%3}, {%4,%5,%6,%7}, {%8,%9}, {%0,%1,%2,%3};"                \
        : "+f"(d[0]), "+f"(d[1]), "+f"(d[2]), "+f"(d[3])                       \
        : "r"(a[0]), "r"(a[1]), "r"(a[2]), "r"(a[3]), "r"(b[0]), "r"(b[1]))

// ---------------------------------------------------------------------------
// Shared GEMM macro-structure:
//   CTA tile 128(m) x 128(n), BK=32, 8 warps as 2(m) x 4(n), warp tile 64x32.
//   A: row-major [*, ldA] K-contiguous; B: row-major [*, ldB] K-contiguous (NT).
//   Register-prefetch pipelining; tf32 conversion at smem fill.
// ---------------------------------------------------------------------------

// GEMM1: h = relu(hidden @ proj_w^T + bias).  M=8192, N=256, K=1024.
__global__ __launch_bounds__(256, 1)
void proj_relu_mma(const float* __restrict__ A,      // [M, K]
                   const float* __restrict__ W,      // [N, K]
                   const float* __restrict__ bias,   // [N]
                   float* __restrict__ C)            // [M, N]
{
    __shared__ uint32_t As[128 * LDSP];
    __shared__ uint32_t Bs[128 * LDSP];

    const int tid  = threadIdx.x;
    const int warp = tid >> 5, lane = tid & 31;
    const int gid  = lane >> 2, tig = lane & 3;
    const int wm   = (warp & 1) * 64;     // warp m-offset
    const int wn   = (warp >> 1) * 32;    // warp n-offset

    const int K = DMODEL, N = DPROJ;
    const float* Ab = A + (size_t)(blockIdx.y * 128) * K;
    const float* Bb = W + (size_t)(blockIdx.x * 128) * K;

    const int lr = tid >> 3;            // 0..31: row within 32-row pass
    const int lq = (tid & 7) * 4;       // 0..28: k-offset (float4 quad)

    float acc[4][4][4];
    #pragma unroll
    for (int i = 0; i < 4; i++)
        #pragma unroll
        for (int j = 0; j < 4; j++)
            #pragma unroll
            for (int v = 0; v < 4; v++) acc[i][j][v] = 0.0f;

    float4 ra[4], rb[4];
    // prologue: load k-tile 0
    #pragma unroll
    for (int p = 0; p < 4; p++) {
        ra[p] = *(const float4*)(Ab + (size_t)(p * 32 + lr) * K + lq);
        rb[p] = *(const float4*)(Bb + (size_t)(p * 32 + lr) * K + lq);
    }
    #pragma unroll
    for (int p = 0; p < 4; p++) {
        uint4 ua = {f2tf32(ra[p].x), f2tf32(ra[p].y), f2tf32(ra[p].z), f2tf32(ra[p].w)};
        uint4 ub = {f2tf32(rb[p].x), f2tf32(rb[p].y), f2tf32(rb[p].z), f2tf32(rb[p].w)};
        *(uint4*)&As[(p * 32 + lr) * LDSP + lq] = ua;
        *(uint4*)&Bs[(p * 32 + lr) * LDSP + lq] = ub;
    }
    __syncthreads();

    const int NITER = K / BKF;
    for (int it = 0; it < NITER; it++) {
        const bool has_next = (it + 1) < NITER;
        if (has_next) {
            const int kn = (it + 1) * BKF;
            #pragma unroll
            for (int p = 0; p < 4; p++) {
                ra[p] = *(const float4*)(Ab + (size_t)(p * 32 + lr) * K + kn + lq);
                rb[p] = *(const float4*)(Bb + (size_t)(p * 32 + lr) * K + kn + lq);
            }
        }
        #pragma unroll
        for (int ks = 0; ks < 4; ks++) {
            const int k0 = ks * 8;
            uint32_t af[4][4], bf[4][2];
            #pragma unroll
            for (int mt = 0; mt < 4; mt++) {
                const int r = wm + mt * 16;
                af[mt][0] = As[(r + gid    ) * LDSP + k0 + tig    ];
                af[mt][1] = As[(r + gid + 8) * LDSP + k0 + tig    ];
                af[mt][2] = As[(r + gid    ) * LDSP + k0 + tig + 4];
                af[mt][3] = As[(r + gid + 8) * LDSP + k0 + tig + 4];
            }
            #pragma unroll
            for (int nt = 0; nt < 4; nt++) {
                const int c = wn + nt * 8;
                bf[nt][0] = Bs[(c + gid) * LDSP + k0 + tig    ];
                bf[nt][1] = Bs[(c + gid) * LDSP + k0 + tig + 4];
            }
            #pragma unroll
            for (int mt = 0; mt < 4; mt++)
                #pragma unroll
                for (int nt = 0; nt < 4; nt++)
                    MMA_TF32(acc[mt][nt], af[mt], bf[nt]);
        }
        __syncthreads();
        if (has_next) {
            #pragma unroll
            for (int p = 0; p < 4; p++) {
                uint4 ua = {f2tf32(ra[p].x), f2tf32(ra[p].y), f2tf32(ra[p].z), f2tf32(ra[p].w)};
                uint4 ub = {f2tf32(rb[p].x), f2tf32(rb[p].y), f2tf32(rb[p].z), f2tf32(rb[p].w)};
                *(uint4*)&As[(p * 32 + lr) * LDSP + lq] = ua;
                *(uint4*)&Bs[(p * 32 + lr) * LDSP + lq] = ub;
            }
            __syncthreads();
        }
    }

    // epilogue: + bias, relu
    #pragma unroll
    for (int mt = 0; mt < 4; mt++) {
        const int row0 = blockIdx.y * 128 + wm + mt * 16 + gid;
        #pragma unroll
        for (int nt = 0; nt < 4; nt++) {
            const int col0 = blockIdx.x * 128 + wn + nt * 8 + 2 * tig;
            const float b0 = bias[col0], b1 = bias[col0 + 1];
            float2 v0, v1;
            v0.x = fmaxf(acc[mt][nt][0] + b0, 0.0f);
            v0.y = fmaxf(acc[mt][nt][1] + b1, 0.0f);
            v1.x = fmaxf(acc[mt][nt][2] + b0, 0.0f);
            v1.y = fmaxf(acc[mt][nt][3] + b1, 0.0f);
            *(float2*)(C + (size_t)row0 * N + col0)       = v0;
            *(float2*)(C + (size_t)(row0 + 8) * N + col0) = v1;
        }
    }
}

// GEMM2: out[b] = (h[b] @ h[b]^T) * clf_w + clf_b.  Per batch: M=N=2048, K=256.
__global__ __launch_bounds__(256, 1)
void scores_mma(const float* __restrict__ H,
                float* __restrict__ C,
                const float* __restrict__ clf_w,
                const float* __restrict__ clf_b)
{
    __shared__ uint32_t As[128 * LDSP];
    __shared__ uint32_t Bs[128 * LDSP];

    const int tid  = threadIdx.x;
    const int warp = tid >> 5, lane = tid & 31;
    const int gid  = lane >> 2, tig = lane & 3;
    const int wm   = (warp & 1) * 64;
    const int wn   = (warp >> 1) * 32;

    const int K = DPROJ, N = SEQ;
    const float* Hb = H + (size_t)blockIdx.z * SEQ * DPROJ;
    float* Cb = C + (size_t)blockIdx.z * SEQ * SEQ;
    const float* Ab = Hb + (size_t)(blockIdx.y * 128) * K;
    const float* Bb = Hb + (size_t)(blockIdx.x * 128) * K;

    const int lr = tid >> 3;
    const int lq = (tid & 7) * 4;

    float acc[4][4][4];
    #pragma unroll
    for (int i = 0; i < 4; i++)
        #pragma unroll
        for (int j = 0; j < 4; j++)
            #pragma unroll
            for (int v = 0; v < 4; v++) acc[i][j][v] = 0.0f;

    float4 ra[4], rb[4];
    #pragma unroll
    for (int p = 0; p < 4; p++) {
        ra[p] = *(const float4*)(Ab + (size_t)(p * 32 + lr) * K + lq);
        rb[p] = *(const float4*)(Bb + (size_t)(p * 32 + lr) * K + lq);
    }
    #pragma unroll
    for (int p = 0; p < 4; p++) {
        uint4 ua = {f2tf32(ra[p].x), f2tf32(ra[p].y), f2tf32(ra[p].z), f2tf32(ra[p].w)};
        uint4 ub = {f2tf32(rb[p].x), f2tf32(rb[p].y), f2tf32(rb[p].z), f2tf32(rb[p].w)};
        *(uint4*)&As[(p * 32 + lr) * LDSP + lq] = ua;
        *(uint4*)&Bs[(p * 32 + lr) * LDSP + lq] = ub;
    }
    __syncthreads();

    const int NITER = K / BKF;   // 8
    for (int it = 0; it < NITER; it++) {
        const bool has_next = (it + 1) < NITER;
        if (has_next) {
            const int kn = (it + 1) * BKF;
            #pragma unroll
            for (int p = 0; p < 4; p++) {
                ra[p] = *(const float4*)(Ab + (size_t)(p * 32 + lr) * K + kn + lq);
                rb[p] = *(const float4*)(Bb + (size_t)(p * 32 + lr) * K + kn + lq);
            }
        }
        #pragma unroll
        for (int ks = 0; ks < 4; ks++) {
            const int k0 = ks * 8;
            uint32_t af[4][4], bf[4][2];
            #pragma unroll
            for (int mt = 0; mt < 4; mt++) {
                const int r = wm + mt * 16;
                af[mt][0] = As[(r + gid    ) * LDSP + k0 + tig    ];
                af[mt][1] = As[(r + gid + 8) * LDSP + k0 + tig    ];
                af[mt][2] = As[(r + gid    ) * LDSP + k0 + tig + 4];
                af[mt][3] = As[(r + gid + 8) * LDSP + k0 + tig + 4];
            }
            #pragma unroll
            for (int nt = 0; nt < 4; nt++) {
                const int c = wn + nt * 8;
                bf[nt][0] = Bs[(c + gid) * LDSP + k0 + tig    ];
                bf[nt][1] = Bs[(c + gid) * LDSP + k0 + tig + 4];
            }
            #pragma unroll
            for (int mt = 0; mt < 4; mt++)
                #pragma unroll
                for (int nt = 0; nt < 4; nt++)
                    MMA_TF32(acc[mt][nt], af[mt], bf[nt]);
        }
        __syncthreads();
        if (has_next) {
            #pragma unroll
            for (int p = 0; p < 4; p++) {
                uint4 ua = {f2tf32(ra[p].x), f2tf32(ra[p].y), f2tf32(ra[p].z), f2tf32(ra[p].w)};
                uint4 ub = {f2tf32(rb[p].x), f2tf32(rb[p].y), f2tf32(rb[p].z), f2tf32(rb[p].w)};
                *(uint4*)&As[(p * 32 + lr) * LDSP + lq] = ua;
                *(uint4*)&Bs[(p * 32 + lr) * LDSP + lq] = ub;
            }
            __syncthreads();
        }
    }

    const float scale = clf_w[0];
    const float shift = clf_b[0];

    #pragma unroll
    for (int mt = 0; mt < 4; mt++) {
        const int row0 = blockIdx.y * 128 + wm + mt * 16 + gid;
        #pragma unroll
        for (int nt = 0; nt < 4; nt++) {
            const int col0 = blockIdx.x * 128 + wn + nt * 8 + 2 * tig;
            float2 v0, v1;
            v0.x = fmaf(acc[mt][nt][0], scale, shift);
            v0.y = fmaf(acc[mt][nt][1], scale, shift);
            v1.x = fmaf(acc[mt][nt][2], scale, shift);
            v1.y = fmaf(acc[mt][nt][3], scale, shift);
            *(float2*)(Cb + (size_t)row0 * N + col0)       = v0;
            *(float2*)(Cb + (size_t)(row0 + 8) * N + col0) = v1;
        }
    }
}

extern "C" void kernel_launch(void* const* d_in, const int* in_sizes, int n_in,
                              void* d_out, int out_size)
{
    const float* hidden = (const float*)d_in[0];  // [4, 2048, 1024]
    const float* proj_w = (const float*)d_in[1];  // [256, 1024]
    const float* proj_b = (const float*)d_in[2];  // [256]
    const float* clf_w  = (const float*)d_in[3];  // [1,1]
    const float* clf_b  = (const float*)d_in[4];  // [1]
    float* out = (float*)d_out;                   // [4, 2048, 2048]

    float* h_scratch;
    cudaGetSymbolAddress((void**)&h_scratch, g_h);

    // GEMM1: h = relu(hidden @ proj_w^T + proj_b)   M=8192, N=256, K=1024
    {
        dim3 grid(DPROJ / 128, (BATCH * SEQ) / 128);   // (2, 64)
        proj_relu_mma<<<grid, 256>>>(hidden, proj_w, proj_b, h_scratch);
    }

    // GEMM2: out[b] = (h[b] @ h[b]^T) * clf_w + clf_b
    {
        dim3 grid(SEQ / 128, SEQ / 128, BATCH);        // (16, 16, 4)
        scores_mma<<<grid, 256>>>(h_scratch, out, clf_w, clf_b);
    }
}

// round 12
// speedup vs baseline: 1.0024x; 1.0024x over previous
#include <cuda_runtime.h>
#include <cstdint>

// Problem constants (fixed by reference setup_inputs)
#define BATCH   4
#define SEQ     2048
#define DMODEL  1024
#define DPROJ   256

#define BKF     32    // K-floats per smem tile
#define LDSP    36    // padded smem row stride (words): bank=(4*row+k)%32 -> conflict-free

// Scratch for h = relu(hidden @ proj_w^T + b): [B, S, P] fp32 = 8 MB
__device__ float g_h[BATCH * SEQ * DPROJ];

__device__ __forceinline__ uint32_t f2tf32(float x) {
    uint32_t r;
    asm("cvt.rna.tf32.f32 %0, %1;" : "=r"(r) : "f"(x));
    return r;
}

#define MMA_TF32(d, a, b)                                                      \
    asm volatile(                                                              \
        "mma.sync.aligned.m16n8k8.row.col.f32.tf32.tf32.f32 "                  \
        "{%0,%1,%2,%3}, {%4,%5,%6,%7}, {%8,%9}, {%0,%1,%2,%3};"                \
        : "+f"(d[0]), "+f"(d[1]), "+f"(d[2]), "+f"(d[3])                       \
        : "r"(a[0]), "r"(a[1]), "r"(a[2]), "r"(a[3]), "r"(b[0]), "r"(b[1]))

// ---------------------------------------------------------------------------
// Shared GEMM macro-structure:
//   CTA tile 128(m) x 128(n), BK=32, 8 warps as 2(m) x 4(n), warp tile 64x32.
//   A: row-major [*, ldA] K-contiguous; B: row-major [*, ldB] K-contiguous (NT).
//   Register-prefetch pipelining; tf32 conversion at smem fill.
// ---------------------------------------------------------------------------

// GEMM1: h = relu(hidden @ proj_w^T + bias).  M=8192, N=256, K=1024.
__global__ __launch_bounds__(256, 1)
void proj_relu_mma(const float* __restrict__ A,      // [M, K]
                   const float* __restrict__ W,      // [N, K]
                   const float* __restrict__ bias,   // [N]
                   float* __restrict__ C)            // [M, N]
{
    __shared__ uint32_t As[128 * LDSP];
    __shared__ uint32_t Bs[128 * LDSP];

    const int tid  = threadIdx.x;
    const int warp = tid >> 5, lane = tid & 31;
    const int gid  = lane >> 2, tig = lane & 3;
    const int wm   = (warp & 1) * 64;     // warp m-offset
    const int wn   = (warp >> 1) * 32;    // warp n-offset

    const int K = DMODEL, N = DPROJ;
    const float* Ab = A + (size_t)(blockIdx.y * 128) * K;
    const float* Bb = W + (size_t)(blockIdx.x * 128) * K;

    const int lr = tid >> 3;            // 0..31: row within 32-row pass
    const int lq = (tid & 7) * 4;       // 0..28: k-offset (float4 quad)

    float acc[4][4][4];
    #pragma unroll
    for (int i = 0; i < 4; i++)
        #pragma unroll
        for (int j = 0; j < 4; j++)
            #pragma unroll
            for (int v = 0; v < 4; v++) acc[i][j][v] = 0.0f;

    float4 ra[4], rb[4];
    // prologue: load k-tile 0
    #pragma unroll
    for (int p = 0; p < 4; p++) {
        ra[p] = *(const float4*)(Ab + (size_t)(p * 32 + lr) * K + lq);
        rb[p] = *(const float4*)(Bb + (size_t)(p * 32 + lr) * K + lq);
    }
    #pragma unroll
    for (int p = 0; p < 4; p++) {
        uint4 ua = {f2tf32(ra[p].x), f2tf32(ra[p].y), f2tf32(ra[p].z), f2tf32(ra[p].w)};
        uint4 ub = {f2tf32(rb[p].x), f2tf32(rb[p].y), f2tf32(rb[p].z), f2tf32(rb[p].w)};
        *(uint4*)&As[(p * 32 + lr) * LDSP + lq] = ua;
        *(uint4*)&Bs[(p * 32 + lr) * LDSP + lq] = ub;
    }
    __syncthreads();

    const int NITER = K / BKF;
    for (int it = 0; it < NITER; it++) {
        const bool has_next = (it + 1) < NITER;
        if (has_next) {
            const int kn = (it + 1) * BKF;
            #pragma unroll
            for (int p = 0; p < 4; p++) {
                ra[p] = *(const float4*)(Ab + (size_t)(p * 32 + lr) * K + kn + lq);
                rb[p] = *(const float4*)(Bb + (size_t)(p * 32 + lr) * K + kn + lq);
            }
        }
        #pragma unroll
        for (int ks = 0; ks < 4; ks++) {
            const int k0 = ks * 8;
            uint32_t af[4][4], bf[4][2];
            #pragma unroll
            for (int mt = 0; mt < 4; mt++) {
                const int r = wm + mt * 16;
                af[mt][0] = As[(r + gid    ) * LDSP + k0 + tig    ];
                af[mt][1] = As[(r + gid + 8) * LDSP + k0 + tig    ];
                af[mt][2] = As[(r + gid    ) * LDSP + k0 + tig + 4];
                af[mt][3] = As[(r + gid + 8) * LDSP + k0 + tig + 4];
            }
            #pragma unroll
            for (int nt = 0; nt < 4; nt++) {
                const int c = wn + nt * 8;
                bf[nt][0] = Bs[(c + gid) * LDSP + k0 + tig    ];
                bf[nt][1] = Bs[(c + gid) * LDSP + k0 + tig + 4];
            }
            #pragma unroll
            for (int mt = 0; mt < 4; mt++)
                #pragma unroll
                for (int nt = 0; nt < 4; nt++)
                    MMA_TF32(acc[mt][nt], af[mt], bf[nt]);
        }
        __syncthreads();
        if (has_next) {
            #pragma unroll
            for (int p = 0; p < 4; p++) {
                uint4 ua = {f2tf32(ra[p].x), f2tf32(ra[p].y), f2tf32(ra[p].z), f2tf32(ra[p].w)};
                uint4 ub = {f2tf32(rb[p].x), f2tf32(rb[p].y), f2tf32(rb[p].z), f2tf32(rb[p].w)};
                *(uint4*)&As[(p * 32 + lr) * LDSP + lq] = ua;
                *(uint4*)&Bs[(p * 32 + lr) * LDSP + lq] = ub;
            }
            __syncthreads();
        }
    }

    // epilogue: + bias, relu
    #pragma unroll
    for (int mt = 0; mt < 4; mt++) {
        const int row0 = blockIdx.y * 128 + wm + mt * 16 + gid;
        #pragma unroll
        for (int nt = 0; nt < 4; nt++) {
            const int col0 = blockIdx.x * 128 + wn + nt * 8 + 2 * tig;
            const float b0 = bias[col0], b1 = bias[col0 + 1];
            float2 v0, v1;
            v0.x = fmaxf(acc[mt][nt][0] + b0, 0.0f);
            v0.y = fmaxf(acc[mt][nt][1] + b1, 0.0f);
            v1.x = fmaxf(acc[mt][nt][2] + b0, 0.0f);
            v1.y = fmaxf(acc[mt][nt][3] + b1, 0.0f);
            *(float2*)(C + (size_t)row0 * N + col0)       = v0;
            *(float2*)(C + (size_t)(row0 + 8) * N + col0) = v1;
        }
    }
}

// GEMM2: out[b] = (h[b] @ h[b]^T) * clf_w + clf_b.  Per batch: M=N=2048, K=256.
__global__ __launch_bounds__(256, 1)
void scores_mma(const float* __restrict__ H,
                float* __restrict__ C,
                const float* __restrict__ clf_w,
                const float* __restrict__ clf_b)
{
    __shared__ uint32_t As[128 * LDSP];
    __shared__ uint32_t Bs[128 * LDSP];

    const int tid  = threadIdx.x;
    const int warp = tid >> 5, lane = tid & 31;
    const int gid  = lane >> 2, tig = lane & 3;
    const int wm   = (warp & 1) * 64;
    const int wn   = (warp >> 1) * 32;

    const int K = DPROJ, N = SEQ;
    const float* Hb = H + (size_t)blockIdx.z * SEQ * DPROJ;
    float* Cb = C + (size_t)blockIdx.z * SEQ * SEQ;
    const float* Ab = Hb + (size_t)(blockIdx.y * 128) * K;
    const float* Bb = Hb + (size_t)(blockIdx.x * 128) * K;

    const int lr = tid >> 3;
    const int lq = (tid & 7) * 4;

    float acc[4][4][4];
    #pragma unroll
    for (int i = 0; i < 4; i++)
        #pragma unroll
        for (int j = 0; j < 4; j++)
            #pragma unroll
            for (int v = 0; v < 4; v++) acc[i][j][v] = 0.0f;

    float4 ra[4], rb[4];
    #pragma unroll
    for (int p = 0; p < 4; p++) {
        ra[p] = *(const float4*)(Ab + (size_t)(p * 32 + lr) * K + lq);
        rb[p] = *(const float4*)(Bb + (size_t)(p * 32 + lr) * K + lq);
    }
    #pragma unroll
    for (int p = 0; p < 4; p++) {
        uint4 ua = {f2tf32(ra[p].x), f2tf32(ra[p].y), f2tf32(ra[p].z), f2tf32(ra[p].w)};
        uint4 ub = {f2tf32(rb[p].x), f2tf32(rb[p].y), f2tf32(rb[p].z), f2tf32(rb[p].w)};
        *(uint4*)&As[(p * 32 + lr) * LDSP + lq] = ua;
        *(uint4*)&Bs[(p * 32 + lr) * LDSP + lq] = ub;
    }
    __syncthreads();

    const int NITER = K / BKF;   // 8
    for (int it = 0; it < NITER; it++) {
        const bool has_next = (it + 1) < NITER;
        if (has_next) {
            const int kn = (it + 1) * BKF;
            #pragma unroll
            for (int p = 0; p < 4; p++) {
                ra[p] = *(const float4*)(Ab + (size_t)(p * 32 + lr) * K + kn + lq);
                rb[p] = *(const float4*)(Bb + (size_t)(p * 32 + lr) * K + kn + lq);
            }
        }
        #pragma unroll
        for (int ks = 0; ks < 4; ks++) {
            const int k0 = ks * 8;
            uint32_t af[4][4], bf[4][2];
            #pragma unroll
            for (int mt = 0; mt < 4; mt++) {
                const int r = wm + mt * 16;
                af[mt][0] = As[(r + gid    ) * LDSP + k0 + tig    ];
                af[mt][1] = As[(r + gid + 8) * LDSP + k0 + tig    ];
                af[mt][2] = As[(r + gid    ) * LDSP + k0 + tig + 4];
                af[mt][3] = As[(r + gid + 8) * LDSP + k0 + tig + 4];
            }
            #pragma unroll
            for (int nt = 0; nt < 4; nt++) {
                const int c = wn + nt * 8;
                bf[nt][0] = Bs[(c + gid) * LDSP + k0 + tig    ];
                bf[nt][1] = Bs[(c + gid) * LDSP + k0 + tig + 4];
            }
            #pragma unroll
            for (int mt = 0; mt < 4; mt++)
                #pragma unroll
                for (int nt = 0; nt < 4; nt++)
                    MMA_TF32(acc[mt][nt], af[mt], bf[nt]);
        }
        __syncthreads();
        if (has_next) {
            #pragma unroll
            for (int p = 0; p < 4; p++) {
                uint4 ua = {f2tf32(ra[p].x), f2tf32(ra[p].y), f2tf32(ra[p].z), f2tf32(ra[p].w)};
                uint4 ub = {f2tf32(rb[p].x), f2tf32(rb[p].y), f2tf32(rb[p].z), f2tf32(rb[p].w)};
                *(uint4*)&As[(p * 32 + lr) * LDSP + lq] = ua;
                *(uint4*)&Bs[(p * 32 + lr) * LDSP + lq] = ub;
            }
            __syncthreads();
        }
    }

    const float scale = clf_w[0];
    const float shift = clf_b[0];

    #pragma unroll
    for (int mt = 0; mt < 4; mt++) {
        const int row0 = blockIdx.y * 128 + wm + mt * 16 + gid;
        #pragma unroll
        for (int nt = 0; nt < 4; nt++) {
            const int col0 = blockIdx.x * 128 + wn + nt * 8 + 2 * tig;
            float2 v0, v1;
            v0.x = fmaf(acc[mt][nt][0], scale, shift);
            v0.y = fmaf(acc[mt][nt][1], scale, shift);
            v1.x = fmaf(acc[mt][nt][2], scale, shift);
            v1.y = fmaf(acc[mt][nt][3], scale, shift);
            *(float2*)(Cb + (size_t)row0 * N + col0)       = v0;
            *(float2*)(Cb + (size_t)(row0 + 8) * N + col0) = v1;
        }
    }
}

extern "C" void kernel_launch(void* const* d_in, const int* in_sizes, int n_in,
                              void* d_out, int out_size)
{
    const float* hidden = (const float*)d_in[0];  // [4, 2048, 1024]
    const float* proj_w = (const float*)d_in[1];  // [256, 1024]
    const float* proj_b = (const float*)d_in[2];  // [256]
    const float* clf_w  = (const float*)d_in[3];  // [1,1]
    const float* clf_b  = (const float*)d_in[4];  // [1]
    float* out = (float*)d_out;                   // [4, 2048, 2048]

    float* h_scratch;
    cudaGetSymbolAddress((void**)&h_scratch, g_h);

    // GEMM1: h = relu(hidden @ proj_w^T + proj_b)   M=8192, N=256, K=1024
    {
        dim3 grid(DPROJ / 128, (BATCH * SEQ) / 128);   // (2, 64)
        proj_relu_mma<<<grid, 256>>>(hidden, proj_w, proj_b, h_scratch);
    }

    // GEMM2: out[b] = (h[b] @ h[b]^T) * clf_w + clf_b
    {
        dim3 grid(SEQ / 128, SEQ / 128, BATCH);        // (16, 16, 4)
        scores_mma<<<grid, 256>>>(h_scratch, out, clf_w, clf_b);
    }
}

// round 13
// speedup vs baseline: 1.0030x; 1.0005x over previous
#include <cuda_runtime.h>
#include <cstdint>

// Problem constants (fixed by reference setup_inputs)
#define BATCH   4
#define SEQ     2048
#define DMODEL  1024
#define DPROJ   256

#define BKF     32    // K-floats per smem tile
#define LDSP    36    // padded smem row stride (words): bank=(4*row+k)%32 -> conflict-free

// Scratch for h = relu(hidden @ proj_w^T + b): [B, S, P] fp32 = 8 MB
__device__ float g_h[BATCH * SEQ * DPROJ];

__device__ __forceinline__ uint32_t f2tf32(float x) {
    uint32_t r;
    asm("cvt.rna.tf32.f32 %0, %1;" : "=r"(r) : "f"(x));
    return r;
}

#define MMA_TF32(d, a, b)                                                      \
    asm volatile(                                                              \
        "mma.sync.aligned.m16n8k8.row.col.f32.tf32.tf32.f32 "                  \
        "{%0,%1,%2,%3}, {%4,%5,%6,%7}, {%8,%9}, {%0,%1,%2,%3};"                \
        : "+f"(d[0]), "+f"(d[1]), "+f"(d[2]), "+f"(d[3])                       \
        : "r"(a[0]), "r"(a[1]), "r"(a[2]), "r"(a[3]), "r"(b[0]), "r"(b[1]))

// ---------------------------------------------------------------------------
// Shared GEMM macro-structure:
//   CTA tile 128(m) x 128(n), BK=32, 8 warps as 2(m) x 4(n), warp tile 64x32.
//   A: row-major [*, ldA] K-contiguous; B: row-major [*, ldB] K-contiguous (NT).
//   Register-prefetch pipelining; tf32 conversion at smem fill.
// ---------------------------------------------------------------------------

// GEMM1: h = relu(hidden @ proj_w^T + bias).  M=8192, N=256, K=1024.
__global__ __launch_bounds__(256, 1)
void proj_relu_mma(const float* __restrict__ A,      // [M, K]
                   const float* __restrict__ W,      // [N, K]
                   const float* __restrict__ bias,   // [N]
                   float* __restrict__ C)            // [M, N]
{
    __shared__ uint32_t As[128 * LDSP];
    __shared__ uint32_t Bs[128 * LDSP];

    const int tid  = threadIdx.x;
    const int warp = tid >> 5, lane = tid & 31;
    const int gid  = lane >> 2, tig = lane & 3;
    const int wm   = (warp & 1) * 64;     // warp m-offset
    const int wn   = (warp >> 1) * 32;    // warp n-offset

    const int K = DMODEL, N = DPROJ;
    const float* Ab = A + (size_t)(blockIdx.y * 128) * K;
    const float* Bb = W + (size_t)(blockIdx.x * 128) * K;

    const int lr = tid >> 3;            // 0..31: row within 32-row pass
    const int lq = (tid & 7) * 4;       // 0..28: k-offset (float4 quad)

    float acc[4][4][4];
    #pragma unroll
    for (int i = 0; i < 4; i++)
        #pragma unroll
        for (int j = 0; j < 4; j++)
            #pragma unroll
            for (int v = 0; v < 4; v++) acc[i][j][v] = 0.0f;

    float4 ra[4], rb[4];
    // prologue: load k-tile 0
    #pragma unroll
    for (int p = 0; p < 4; p++) {
        ra[p] = *(const float4*)(Ab + (size_t)(p * 32 + lr) * K + lq);
        rb[p] = *(const float4*)(Bb + (size_t)(p * 32 + lr) * K + lq);
    }
    #pragma unroll
    for (int p = 0; p < 4; p++) {
        uint4 ua = {f2tf32(ra[p].x), f2tf32(ra[p].y), f2tf32(ra[p].z), f2tf32(ra[p].w)};
        uint4 ub = {f2tf32(rb[p].x), f2tf32(rb[p].y), f2tf32(rb[p].z), f2tf32(rb[p].w)};
        *(uint4*)&As[(p * 32 + lr) * LDSP + lq] = ua;
        *(uint4*)&Bs[(p * 32 + lr) * LDSP + lq] = ub;
    }
    __syncthreads();

    const int NITER = K / BKF;
    for (int it = 0; it < NITER; it++) {
        const bool has_next = (it + 1) < NITER;
        if (has_next) {
            const int kn = (it + 1) * BKF;
            #pragma unroll
            for (int p = 0; p < 4; p++) {
                ra[p] = *(const float4*)(Ab + (size_t)(p * 32 + lr) * K + kn + lq);
                rb[p] = *(const float4*)(Bb + (size_t)(p * 32 + lr) * K + kn + lq);
            }
        }
        #pragma unroll
        for (int ks = 0; ks < 4; ks++) {
            const int k0 = ks * 8;
            uint32_t af[4][4], bf[4][2];
            #pragma unroll
            for (int mt = 0; mt < 4; mt++) {
                const int r = wm + mt * 16;
                af[mt][0] = As[(r + gid    ) * LDSP + k0 + tig    ];
                af[mt][1] = As[(r + gid + 8) * LDSP + k0 + tig    ];
                af[mt][2] = As[(r + gid    ) * LDSP + k0 + tig + 4];
                af[mt][3] = As[(r + gid + 8) * LDSP + k0 + tig + 4];
            }
            #pragma unroll
            for (int nt = 0; nt < 4; nt++) {
                const int c = wn + nt * 8;
                bf[nt][0] = Bs[(c + gid) * LDSP + k0 + tig    ];
                bf[nt][1] = Bs[(c + gid) * LDSP + k0 + tig + 4];
            }
            #pragma unroll
            for (int mt = 0; mt < 4; mt++)
                #pragma unroll
                for (int nt = 0; nt < 4; nt++)
                    MMA_TF32(acc[mt][nt], af[mt], bf[nt]);
        }
        __syncthreads();
        if (has_next) {
            #pragma unroll
            for (int p = 0; p < 4; p++) {
                uint4 ua = {f2tf32(ra[p].x), f2tf32(ra[p].y), f2tf32(ra[p].z), f2tf32(ra[p].w)};
                uint4 ub = {f2tf32(rb[p].x), f2tf32(rb[p].y), f2tf32(rb[p].z), f2tf32(rb[p].w)};
                *(uint4*)&As[(p * 32 + lr) * LDSP + lq] = ua;
                *(uint4*)&Bs[(p * 32 + lr) * LDSP + lq] = ub;
            }
            __syncthreads();
        }
    }

    // epilogue: + bias, relu
    #pragma unroll
    for (int mt = 0; mt < 4; mt++) {
        const int row0 = blockIdx.y * 128 + wm + mt * 16 + gid;
        #pragma unroll
        for (int nt = 0; nt < 4; nt++) {
            const int col0 = blockIdx.x * 128 + wn + nt * 8 + 2 * tig;
            const float b0 = bias[col0], b1 = bias[col0 + 1];
            float2 v0, v1;
            v0.x = fmaxf(acc[mt][nt][0] + b0, 0.0f);
            v0.y = fmaxf(acc[mt][nt][1] + b1, 0.0f);
            v1.x = fmaxf(acc[mt][nt][2] + b0, 0.0f);
            v1.y = fmaxf(acc[mt][nt][3] + b1, 0.0f);
            *(float2*)(C + (size_t)row0 * N + col0)       = v0;
            *(float2*)(C + (size_t)(row0 + 8) * N + col0) = v1;
        }
    }
}

// GEMM2: out[b] = (h[b] @ h[b]^T) * clf_w + clf_b.  Per batch: M=N=2048, K=256.
__global__ __launch_bounds__(256, 1)
void scores_mma(const float* __restrict__ H,
                float* __restrict__ C,
                const float* __restrict__ clf_w,
                const float* __restrict__ clf_b)
{
    __shared__ uint32_t As[128 * LDSP];
    __shared__ uint32_t Bs[128 * LDSP];

    const int tid  = threadIdx.x;
    const int warp = tid >> 5, lane = tid & 31;
    const int gid  = lane >> 2, tig = lane & 3;
    const int wm   = (warp & 1) * 64;
    const int wn   = (warp >> 1) * 32;

    const int K = DPROJ, N = SEQ;
    const float* Hb = H + (size_t)blockIdx.z * SEQ * DPROJ;
    float* Cb = C + (size_t)blockIdx.z * SEQ * SEQ;
    const float* Ab = Hb + (size_t)(blockIdx.y * 128) * K;
    const float* Bb = Hb + (size_t)(blockIdx.x * 128) * K;

    const int lr = tid >> 3;
    const int lq = (tid & 7) * 4;

    float acc[4][4][4];
    #pragma unroll
    for (int i = 0; i < 4; i++)
        #pragma unroll
        for (int j = 0; j < 4; j++)
            #pragma unroll
            for (int v = 0; v < 4; v++) acc[i][j][v] = 0.0f;

    float4 ra[4], rb[4];
    #pragma unroll
    for (int p = 0; p < 4; p++) {
        ra[p] = *(const float4*)(Ab + (size_t)(p * 32 + lr) * K + lq);
        rb[p] = *(const float4*)(Bb + (size_t)(p * 32 + lr) * K + lq);
    }
    #pragma unroll
    for (int p = 0; p < 4; p++) {
        uint4 ua = {f2tf32(ra[p].x), f2tf32(ra[p].y), f2tf32(ra[p].z), f2tf32(ra[p].w)};
        uint4 ub = {f2tf32(rb[p].x), f2tf32(rb[p].y), f2tf32(rb[p].z), f2tf32(rb[p].w)};
        *(uint4*)&As[(p * 32 + lr) * LDSP + lq] = ua;
        *(uint4*)&Bs[(p * 32 + lr) * LDSP + lq] = ub;
    }
    __syncthreads();

    const int NITER = K / BKF;   // 8
    for (int it = 0; it < NITER; it++) {
        const bool has_next = (it + 1) < NITER;
        if (has_next) {
            const int kn = (it + 1) * BKF;
            #pragma unroll
            for (int p = 0; p < 4; p++) {
                ra[p] = *(const float4*)(Ab + (size_t)(p * 32 + lr) * K + kn + lq);
                rb[p] = *(const float4*)(Bb + (size_t)(p * 32 + lr) * K + kn + lq);
            }
        }
        #pragma unroll
        for (int ks = 0; ks < 4; ks++) {
            const int k0 = ks * 8;
            uint32_t af[4][4], bf[4][2];
            #pragma unroll
            for (int mt = 0; mt < 4; mt++) {
                const int r = wm + mt * 16;
                af[mt][0] = As[(r + gid    ) * LDSP + k0 + tig    ];
                af[mt][1] = As[(r + gid + 8) * LDSP + k0 + tig    ];
                af[mt][2] = As[(r + gid    ) * LDSP + k0 + tig + 4];
                af[mt][3] = As[(r + gid + 8) * LDSP + k0 + tig + 4];
            }
            #pragma unroll
            for (int nt = 0; nt < 4; nt++) {
                const int c = wn + nt * 8;
                bf[nt][0] = Bs[(c + gid) * LDSP + k0 + tig    ];
                bf[nt][1] = Bs[(c + gid) * LDSP + k0 + tig + 4];
            }
            #pragma unroll
            for (int mt = 0; mt < 4; mt++)
                #pragma unroll
                for (int nt = 0; nt < 4; nt++)
                    MMA_TF32(acc[mt][nt], af[mt], bf[nt]);
        }
        __syncthreads();
        if (has_next) {
            #pragma unroll
            for (int p = 0; p < 4; p++) {
                uint4 ua = {f2tf32(ra[p].x), f2tf32(ra[p].y), f2tf32(ra[p].z), f2tf32(ra[p].w)};
                uint4 ub = {f2tf32(rb[p].x), f2tf32(rb[p].y), f2tf32(rb[p].z), f2tf32(rb[p].w)};
                *(uint4*)&As[(p * 32 + lr) * LDSP + lq] = ua;
                *(uint4*)&Bs[(p * 32 + lr) * LDSP + lq] = ub;
            }
            __syncthreads();
        }
    }

    const float scale = clf_w[0];
    const float shift = clf_b[0];

    #pragma unroll
    for (int mt = 0; mt < 4; mt++) {
        const int row0 = blockIdx.y * 128 + wm + mt * 16 + gid;
        #pragma unroll
        for (int nt = 0; nt < 4; nt++) {
            const int col0 = blockIdx.x * 128 + wn + nt * 8 + 2 * tig;
            float2 v0, v1;
            v0.x = fmaf(acc[mt][nt][0], scale, shift);
            v0.y = fmaf(acc[mt][nt][1], scale, shift);
            v1.x = fmaf(acc[mt][nt][2], scale, shift);
            v1.y = fmaf(acc[mt][nt][3], scale, shift);
            *(float2*)(Cb + (size_t)row0 * N + col0)       = v0;
            *(float2*)(Cb + (size_t)(row0 + 8) * N + col0) = v1;
        }
    }
}

extern "C" void kernel_launch(void* const* d_in, const int* in_sizes, int n_in,
                              void* d_out, int out_size)
{
    const float* hidden = (const float*)d_in[0];  // [4, 2048, 1024]
    const float* proj_w = (const float*)d_in[1];  // [256, 1024]
    const float* proj_b = (const float*)d_in[2];  // [256]
    const float* clf_w  = (const float*)d_in[3];  // [1,1]
    const float* clf_b  = (const float*)d_in[4];  // [1]
    float* out = (float*)d_out;                   // [4, 2048, 2048]

    float* h_scratch;
    cudaGetSymbolAddress((void**)&h_scratch, g_h);

    // GEMM1: h = relu(hidden @ proj_w^T + proj_b)   M=8192, N=256, K=1024
    {
        dim3 grid(DPROJ / 128, (BATCH * SEQ) / 128);   // (2, 64)
        proj_relu_mma<<<grid, 256>>>(hidden, proj_w, proj_b, h_scratch);
    }

    // GEMM2: out[b] = (h[b] @ h[b]^T) * clf_w + clf_b
    {
        dim3 grid(SEQ / 128, SEQ / 128, BATCH);        // (16, 16, 4)
        scores_mma<<<grid, 256>>>(h_scratch, out, clf_w, clf_b);
    }
}